// round 2
// baseline (speedup 1.0000x reference)
#include <cuda_runtime.h>

#define VOCAB 10000
#define EMBED 300
#define BATCH 262144

__device__ double g_acc;

__global__ void glove_zero_kernel() {
    g_acc = 0.0;
}

__global__ void glove_main_kernel(const int* __restrict__ ci,
                                  const int* __restrict__ cj,
                                  const float* __restrict__ V,
                                  const float* __restrict__ U,
                                  const float* __restrict__ vb,
                                  const float* __restrict__ ub,
                                  const float* __restrict__ comat) {
    const int warp_global = (blockIdx.x * blockDim.x + threadIdx.x) >> 5;
    const int lane = threadIdx.x & 31;

    __shared__ double ssum;
    if (threadIdx.x == 0) ssum = 0.0;
    __syncthreads();

    float contrib = 0.0f;
    if (warp_global < BATCH) {
        const int i = ci[warp_global];
        const int j = cj[warp_global];

        const float4* __restrict__ v4 = (const float4*)(V + (size_t)i * EMBED);
        const float4* __restrict__ u4 = (const float4*)(U + (size_t)j * EMBED);

        // 300 floats = 75 float4 per row; coalesced strided loads.
        float acc = 0.0f;
        #pragma unroll
        for (int k = 0; k < 3; k++) {
            int idx = lane + k * 32;
            if (idx < 75) {
                float4 a = __ldg(v4 + idx);
                float4 b = __ldg(u4 + idx);
                acc += a.x * b.x + a.y * b.y + a.z * b.z + a.w * b.w;
            }
        }
        // warp reduction
        #pragma unroll
        for (int off = 16; off; off >>= 1)
            acc += __shfl_xor_sync(0xffffffffu, acc, off);

        if (lane == 0) {
            float x = __ldg(comat + (size_t)i * VOCAB + j);
            float w = (x < 100.0f) ? __powf(x * 0.01f, 0.75f) : 1.0f;
            float r = acc + __ldg(vb + i) + __ldg(ub + j) - logf(x);
            contrib = w * r * r;
        }
    }

    if (lane == 0)
        atomicAdd(&ssum, (double)contrib);
    __syncthreads();
    if (threadIdx.x == 0)
        atomicAdd(&g_acc, ssum);
}

__global__ void glove_finish_kernel(float* out) {
    out[0] = (float)g_acc;
}

extern "C" void kernel_launch(void* const* d_in, const int* in_sizes, int n_in,
                              void* d_out, int out_size) {
    const int*   ci    = (const int*)d_in[0];
    const int*   cj    = (const int*)d_in[1];
    const float* V     = (const float*)d_in[2];
    const float* U     = (const float*)d_in[3];
    const float* vb    = (const float*)d_in[4];
    const float* ub    = (const float*)d_in[5];
    const float* comat = (const float*)d_in[6];
    float* out = (float*)d_out;

    glove_zero_kernel<<<1, 1>>>();

    const int threads = 256;                 // 8 warps per block
    const int warps_per_block = threads / 32;
    const int blocks = (BATCH + warps_per_block - 1) / warps_per_block;
    glove_main_kernel<<<blocks, threads>>>(ci, cj, V, U, vb, ub, comat);

    glove_finish_kernel<<<1, 1>>>(out);
}

// round 3
// speedup vs baseline: 1.9352x; 1.9352x over previous
#include <cuda_runtime.h>

#define VOCAB 10000
#define EMBED 300
#define BATCH 262144

#define NBLOCKS 2048
#define NTHREADS 256
#define GROUPS_PER_BLOCK (NTHREADS / 8)          // 32 eight-lane groups
#define TOTAL_GROUPS (NBLOCKS * GROUPS_PER_BLOCK) // 65536 -> 4 pairs/group

__device__ float        g_partials[NBLOCKS];
__device__ unsigned int g_count = 0;   // self-resets to 0 each launch

__global__ void __launch_bounds__(NTHREADS)
glove_fused_kernel(const int* __restrict__ ci,
                   const int* __restrict__ cj,
                   const float* __restrict__ V,
                   const float* __restrict__ U,
                   const float* __restrict__ vb,
                   const float* __restrict__ ub,
                   const float* __restrict__ comat,
                   float* __restrict__ out) {
    const int lane = threadIdx.x & 31;
    const int sub  = lane & 7;                       // lane within 8-lane group
    const int wid  = threadIdx.x >> 5;
    const int group_global = blockIdx.x * GROUPS_PER_BLOCK + (threadIdx.x >> 3);

    float gsum = 0.0f;  // only sub==0 lanes accumulate

    for (int p = group_global; p < BATCH; p += TOTAL_GROUPS) {
        const int i = ci[p];
        const int j = cj[p];

        const float4* __restrict__ v4 = (const float4*)(V + (size_t)i * EMBED);
        const float4* __restrict__ u4 = (const float4*)(U + (size_t)j * EMBED);

        // 300 floats = 75 float4 per row; 8 lanes -> 9 full rounds + tail of 3.
        // Fully unrolled: up to ~19 independent loads in flight per thread.
        float acc = 0.0f;
        #pragma unroll
        for (int k = 0; k < 9; k++) {
            float4 a = __ldg(v4 + sub + k * 8);
            float4 b = __ldg(u4 + sub + k * 8);
            acc += a.x * b.x + a.y * b.y + a.z * b.z + a.w * b.w;
        }
        if (sub < 3) {
            float4 a = __ldg(v4 + sub + 72);
            float4 b = __ldg(u4 + sub + 72);
            acc += a.x * b.x + a.y * b.y + a.z * b.z + a.w * b.w;
        }

        // reduce within the 8-lane group
        acc += __shfl_xor_sync(0xffffffffu, acc, 4);
        acc += __shfl_xor_sync(0xffffffffu, acc, 2);
        acc += __shfl_xor_sync(0xffffffffu, acc, 1);

        if (sub == 0) {
            float x = __ldg(comat + (size_t)i * VOCAB + j);
            float w = (x < 100.0f) ? __powf(x * 0.01f, 0.75f) : 1.0f;
            float r = acc + __ldg(vb + i) + __ldg(ub + j) - __logf(x);
            gsum += w * r * r;
        }
    }

    // warp reduce: nonzero only on lanes 0,8,16,24
    gsum += __shfl_xor_sync(0xffffffffu, gsum, 8);
    gsum += __shfl_xor_sync(0xffffffffu, gsum, 16);

    __shared__ float swsum[NTHREADS / 32];
    __shared__ bool  s_last;
    if (lane == 0) swsum[wid] = gsum;
    __syncthreads();

    if (threadIdx.x == 0) {
        float bsum = 0.0f;
        #pragma unroll
        for (int w = 0; w < NTHREADS / 32; w++) bsum += swsum[w];
        g_partials[blockIdx.x] = bsum;
        __threadfence();
        unsigned int t = atomicAdd(&g_count, 1u);
        s_last = (t == (unsigned int)(gridDim.x - 1));
    }
    __syncthreads();

    if (s_last) {
        // last block: reduce all block partials in double
        double d = 0.0;
        for (int k = threadIdx.x; k < NBLOCKS; k += NTHREADS)
            d += (double)g_partials[k];
        #pragma unroll
        for (int off = 16; off; off >>= 1)
            d += __shfl_xor_sync(0xffffffffu, d, off);

        __shared__ double sdw[NTHREADS / 32];
        if (lane == 0) sdw[wid] = d;
        __syncthreads();
        if (threadIdx.x == 0) {
            double total = 0.0;
            #pragma unroll
            for (int w = 0; w < NTHREADS / 32; w++) total += sdw[w];
            out[0] = (float)total;
            g_count = 0;   // reset for next graph replay
        }
    }
}

extern "C" void kernel_launch(void* const* d_in, const int* in_sizes, int n_in,
                              void* d_out, int out_size) {
    const int*   ci    = (const int*)d_in[0];
    const int*   cj    = (const int*)d_in[1];
    const float* V     = (const float*)d_in[2];
    const float* U     = (const float*)d_in[3];
    const float* vb    = (const float*)d_in[4];
    const float* ub    = (const float*)d_in[5];
    const float* comat = (const float*)d_in[6];
    float* out = (float*)d_out;

    glove_fused_kernel<<<NBLOCKS, NTHREADS>>>(ci, cj, V, U, vb, ub, comat, out);
}